// round 15
// baseline (speedup 1.0000x reference)
#include <cuda_runtime.h>
#include <math.h>

// B=4, N=1024, H=64
// out: updated (B,N,H) f32 ++ attn (B,N,N) f32
// softmax shift-invariance: b2 and max-subtraction dropped exactly.

#define Bk 4
#define Nk 1024

// scratch
__device__ float g_A[Bk * Nk * 64];      // A[b*N+i][h] = x@W1a^T + b1
__device__ float g_Ct[Bk * 64 * Nk];     // C^T chunk-major: [b][chunk][h][jc]
__device__ float g_s[Bk * Nk * 4];       // per (row, j-chunk): sum of exp

union F2U { float2 f2; unsigned long long u; float f[2]; };

__device__ __forceinline__ unsigned long long add2(unsigned long long a, unsigned long long b) {
    unsigned long long r;
    asm("add.rn.f32x2 %0, %1, %2;" : "=l"(r) : "l"(a), "l"(b));
    return r;
}
__device__ __forceinline__ unsigned long long fma2(unsigned long long a, unsigned long long b,
                                                   unsigned long long c) {
    unsigned long long r;
    asm("fma.rn.f32x2 %0, %1, %2, %3;" : "=l"(r) : "l"(a), "l"(b), "l"(c));
    return r;
}
__device__ __forceinline__ unsigned int smem_u32(const void* p) {
    unsigned int a;
    asm("{ .reg .u64 t; cvta.to.shared.u64 t, %1; cvt.u32.u64 %0, t; }" : "=r"(a) : "l"(p));
    return a;
}

// ---------------------------------------------------------------------------
// K1: projections (measured-best shape). grid = 128 blocks, 256 threads.
// ---------------------------------------------------------------------------
__global__ __launch_bounds__(256) void k1_proj(const float* __restrict__ x,
                                               const float* __restrict__ W1,
                                               const float* __restrict__ b1)
{
    extern __shared__ float sm1[];
    float2* w1p = (float2*)sm1;              // 32*129 float2: [dp][col]
    float*  xs  = sm1 + 32 * 129 * 2;        // 2048 floats
    float*  sct = xs + 2048;                 // 64*33 floats

    const int t = threadIdx.x;
    const int row0 = blockIdx.x * 32;
    const int b = row0 >> 10;
    const int j0 = row0 & 1023;
    const int tr = t >> 5;
    const int tc = t & 31;

#pragma unroll
    for (int q = 0; q < 8; q++) {
        const int idx4 = q * 256 + t;
        const int h  = idx4 >> 5;
        const int c0 = (idx4 & 31) * 4;
        const int col = (c0 < 64) ? h : h + 64;
        const int dp0 = (c0 & 63) >> 1;
        const float4 v = ((const float4*)W1)[idx4];
        w1p[(dp0 + 0) * 129 + col] = make_float2(v.x, v.y);
        w1p[(dp0 + 1) * 129 + col] = make_float2(v.z, v.w);
    }
#pragma unroll
    for (int q = 0; q < 2; q++)
        ((float4*)xs)[q * 256 + t] = ((const float4*)(x + row0 * 64))[q * 256 + t];
    __syncthreads();

    F2U acc[4][4];
#pragma unroll
    for (int r = 0; r < 4; r++)
#pragma unroll
        for (int k = 0; k < 4; k++) acc[r][k].u = 0ull;

#pragma unroll 8
    for (int dp = 0; dp < 32; dp++) {
        F2U xr[4], wc[4];
#pragma unroll
        for (int r = 0; r < 4; r++)
            xr[r].f2 = *(const float2*)&xs[(tr * 4 + r) * 64 + dp * 2];
#pragma unroll
        for (int k = 0; k < 4; k++)
            wc[k].f2 = w1p[dp * 129 + tc + k * 32];
#pragma unroll
        for (int r = 0; r < 4; r++)
#pragma unroll
            for (int k = 0; k < 4; k++)
                acc[r][k].u = fma2(xr[r].u, wc[k].u, acc[r][k].u);
    }

    const float b0  = b1[tc];
    const float b32 = b1[tc + 32];
#pragma unroll
    for (int r = 0; r < 4; r++) {
        const int jl = tr * 4 + r;
        const int row = row0 + jl;
        g_A[row * 64 + tc]      = acc[r][0].f[0] + acc[r][0].f[1] + b0;
        g_A[row * 64 + tc + 32] = acc[r][1].f[0] + acc[r][1].f[1] + b32;
        sct[tc * 33 + jl]        = acc[r][2].f[0] + acc[r][2].f[1];
        sct[(tc + 32) * 33 + jl] = acc[r][3].f[0] + acc[r][3].f[1];
    }
    __syncthreads();
    {
        const int chunkc = j0 >> 8;
        const int jo     = j0 & 255;
#pragma unroll
        for (int q = 0; q < 8; q++) {
            const int idx = q * 256 + t;
            const int h = idx >> 5, jl = idx & 31;
            g_Ct[b * 65536 + chunkc * 16384 + h * 256 + jo + jl] = sct[h * 33 + jl];
        }
    }
}

// ---------------------------------------------------------------------------
// K2a: exp(logits) + per-chunk sums.  grid = 1024 blocks, 256 threads.
// C chunk staged via one cp.async.bulk into 64KB dyn smem.
// ---------------------------------------------------------------------------
__global__ __launch_bounds__(256) void k2a_logits(const float* __restrict__ W2,
                                                  float* __restrict__ attn)
{
    extern __shared__ __align__(128) float Cs[];     // [64][256] = 64KB
    __shared__ __align__(16) float2 At2[64 * 16];    // {a,a}, [h*16 + i]
    __shared__ float2 w2d[64];
    __shared__ float  reds[8 * 4];
    __shared__ __align__(8) unsigned long long mbar;

    const int t = threadIdx.x;
    const int bid = blockIdx.x;
    const int b     = bid >> 8;
    const int itile = (bid >> 2) & 63;
    const int chunk = bid & 3;
    const int i0 = itile * 16;
    const int j0 = chunk * 256;

    const int ti = t >> 6;
    const int tj = t & 63;

    const unsigned int mb = smem_u32(&mbar);
    if (t == 0) {
        asm volatile("mbarrier.init.shared.b64 [%0], 1;" :: "r"(mb) : "memory");
        asm volatile("mbarrier.arrive.expect_tx.shared.b64 _, [%0], %1;"
                     :: "r"(mb), "r"(65536u) : "memory");
        const float* src = &g_Ct[b * 65536 + chunk * 16384];
        unsigned long long gsrc = (unsigned long long)__cvta_generic_to_global((void*)src);
        asm volatile(
            "cp.async.bulk.shared::cluster.global.mbarrier::complete_tx::bytes "
            "[%0], [%1], %2, [%3];"
            :: "r"(smem_u32(Cs)), "l"(gsrc), "r"(65536u), "r"(mb) : "memory");
    }

    if (t < 64) { const float w = W2[t]; w2d[t] = make_float2(w, w); }
    {
        const int il = t >> 4, h0 = (t & 15) * 4;
        float4 a4 = *(const float4*)&g_A[(b * Nk + i0 + il) * 64 + h0];
        At2[(h0 + 0) * 16 + il] = make_float2(a4.x, a4.x);
        At2[(h0 + 1) * 16 + il] = make_float2(a4.y, a4.y);
        At2[(h0 + 2) * 16 + il] = make_float2(a4.z, a4.z);
        At2[(h0 + 3) * 16 + il] = make_float2(a4.w, a4.w);
    }
    __syncthreads();

    {
        unsigned int done;
        asm volatile(
            "{\n\t.reg .pred p;\n\t"
            "mbarrier.try_wait.parity.acquire.cta.shared::cta.b64 p, [%1], 0;\n\t"
            "selp.b32 %0, 1, 0, p;\n\t}"
            : "=r"(done) : "r"(mb) : "memory");
        if (!done) {
            asm volatile(
                "{\n\t.reg .pred P1;\n\t"
                "WAIT_LOOP_%=:\n\t"
                "mbarrier.try_wait.parity.acquire.cta.shared::cta.b64 P1, [%0], 0, 0x989680;\n\t"
                "@P1 bra.uni WAIT_DONE_%=;\n\t"
                "bra.uni WAIT_LOOP_%=;\n\t"
                "WAIT_DONE_%=:\n\t}"
                :: "r"(mb) : "memory");
        }
    }

    F2U accl[4], acch[4];
#pragma unroll
    for (int ii = 0; ii < 4; ii++) { accl[ii].u = 0ull; acch[ii].u = 0ull; }

#pragma unroll 8
    for (int h = 0; h < 64; h++) {
        const float4 c4 = *(const float4*)&Cs[h * 256 + tj * 4];
        F2U wv; wv.f2 = w2d[h];
        F2U cl, ch; cl.f2 = make_float2(c4.x, c4.y); ch.f2 = make_float2(c4.z, c4.w);
        const float4 a01 = *(const float4*)&At2[h * 16 + ti * 4];
        const float4 a23 = *(const float4*)&At2[h * 16 + ti * 4 + 2];
        F2U ad[4];
        ad[0].f2 = make_float2(a01.x, a01.y);
        ad[1].f2 = make_float2(a01.z, a01.w);
        ad[2].f2 = make_float2(a23.x, a23.y);
        ad[3].f2 = make_float2(a23.z, a23.w);
#pragma unroll
        for (int ii = 0; ii < 4; ii++) {
            F2U v0; v0.u = add2(ad[ii].u, cl.u);
            v0.f[0] = fmaxf(v0.f[0], 0.f); v0.f[1] = fmaxf(v0.f[1], 0.f);
            accl[ii].u = fma2(v0.u, wv.u, accl[ii].u);
            F2U v1; v1.u = add2(ad[ii].u, ch.u);
            v1.f[0] = fmaxf(v1.f[0], 0.f); v1.f[1] = fmaxf(v1.f[1], 0.f);
            acch[ii].u = fma2(v1.u, wv.u, acch[ii].u);
        }
    }

    float* __restrict__ attb = attn + (b * Nk + i0) * Nk + j0;
    float s[4];
#pragma unroll
    for (int ii = 0; ii < 4; ii++) {
        float4 e;
        e.x = __expf(accl[ii].f[0]);  e.y = __expf(accl[ii].f[1]);
        e.z = __expf(acch[ii].f[0]);  e.w = __expf(acch[ii].f[1]);
        *(float4*)&attb[(ti * 4 + ii) * Nk + tj * 4] = e;
        s[ii] = (e.x + e.y) + (e.z + e.w);
    }

#pragma unroll
    for (int off = 16; off > 0; off >>= 1) {
#pragma unroll
        for (int ii = 0; ii < 4; ii++)
            s[ii] += __shfl_xor_sync(0xffffffffu, s[ii], off);
    }
    const int w = t >> 5;
    if ((t & 31) == 0) {
#pragma unroll
        for (int ii = 0; ii < 4; ii++) reds[w * 4 + ii] = s[ii];
    }
    __syncthreads();
    if (t < 16) {
        const int tig = t >> 2, ii = t & 3;
        g_s[(b * Nk + i0 + t) * 4 + chunk] =
            reds[(2 * tig) * 4 + ii] + reds[(2 * tig + 1) * 4 + ii];
    }
}

// ---------------------------------------------------------------------------
// K2b: normalize attn + updated = attn @ x.
// grid = 256 blocks, 512 threads = 16 warps; warp = one j-group of 8 j.
// Thread tile 4i x 8d -> 6 LDS wavefronts per 1024 warp-MACs.
// Dyn smem: xs[128*72] (mid-row +16B pad) ++ psd[16*130 f2] ++ sis[16];
// final 16-partial reduce reuses the first 64KB.
// ---------------------------------------------------------------------------
__global__ __launch_bounds__(512) void k2b_av(const float* __restrict__ x,
                                              float* __restrict__ upd,
                                              float* __restrict__ attn)
{
    extern __shared__ float smdyn[];
    float*  xs    = smdyn;                       // 128*72 = 9216 floats
    float2* psd   = (float2*)(smdyn + 9216);     // 16*130 float2
    float*  sis_s = smdyn + 16384;               // 16 floats (above reduce buffer)
    float*  fb    = smdyn;                       // final partials [row*16+g][64]

    const int t = threadIdx.x;
    const int b  = blockIdx.x >> 6;
    const int i0 = (blockIdx.x & 63) * 16;

    if (t < 16) {
        const float* sr = &g_s[(b * Nk + i0 + t) * 4];
        sis_s[t] = 1.0f / ((sr[0] + sr[1]) + (sr[2] + sr[3]));
    }

    const int g   = t >> 5;            // warp = j-group 0..15
    const int t5  = t & 31;
    const int ti2 = t5 >> 3;           // 0..3 -> rows ti2*4..+3
    const int dg8 = t5 & 7;            // 0..7 -> d = dg8*8..+7
    const int jb  = g * 8;
    const int prow = t >> 5;           // staging row (=g)
    const int pjo  = (t & 31) * 4;     // staging j offset

    const int xoffb = dg8 * 8 + ((dg8 >= 4) ? 4 : 0);

    const float* __restrict__ xb = x + b * Nk * 64;
    float* __restrict__ attb = attn + (b * Nk + i0) * Nk;

    F2U acc[4][4];
#pragma unroll
    for (int ii = 0; ii < 4; ii++)
#pragma unroll
        for (int k = 0; k < 4; k++) acc[ii][k].u = 0ull;

    for (int pass = 0; pass < 8; pass++) {
        const int jt = pass * 128;
        __syncthreads();
        // stage x tile [128][64] with +16B pad mid-row (stride 72)
#pragma unroll
        for (int q = 0; q < 4; q++) {
            const int idx4 = q * 512 + t;
            const int j = idx4 >> 4, d4 = idx4 & 15;
            *(float4*)&xs[j * 72 + d4 * 4 + ((d4 >= 8) ? 4 : 0)] =
                *(const float4*)&xb[(jt + j) * 64 + d4 * 4];
        }
        // normalize probabilities; write attn output + dup'd psd
        {
            const float si = sis_s[prow];
            float4 l0 = *(const float4*)&attb[prow * Nk + jt + pjo];
            float4 p0 = make_float4(l0.x * si, l0.y * si, l0.z * si, l0.w * si);
            *(float4*)&attb[prow * Nk + jt + pjo] = p0;   // final attn
            float2* pd = &psd[prow * 130 + pjo];
            *(float4*)&pd[0] = make_float4(p0.x, p0.x, p0.y, p0.y);
            *(float4*)&pd[2] = make_float4(p0.z, p0.z, p0.w, p0.w);
        }
        __syncthreads();

#pragma unroll
        for (int jj = 0; jj < 8; jj++) {
            const int xo = (jb + jj) * 72 + xoffb;
            const float4 xa = *(const float4*)&xs[xo];
            const float4 xc = *(const float4*)&xs[xo + 4];
            F2U x0, x1, x2, x3;
            x0.f2 = make_float2(xa.x, xa.y);  x1.f2 = make_float2(xa.z, xa.w);
            x2.f2 = make_float2(xc.x, xc.y);  x3.f2 = make_float2(xc.z, xc.w);
#pragma unroll
            for (int ii = 0; ii < 4; ii++) {
                const unsigned long long p2 =
                    *(const unsigned long long*)&psd[(ti2 * 4 + ii) * 130 + jb + jj];
                acc[ii][0].u = fma2(p2, x0.u, acc[ii][0].u);
                acc[ii][1].u = fma2(p2, x1.u, acc[ii][1].u);
                acc[ii][2].u = fma2(p2, x2.u, acc[ii][2].u);
                acc[ii][3].u = fma2(p2, x3.u, acc[ii][3].u);
            }
        }
    }

    // reduce the 16 j-group partials via smem (reuses xs/psd region)
    __syncthreads();
#pragma unroll
    for (int ii = 0; ii < 4; ii++) {
        const int row = ti2 * 4 + ii;
        const int base = (row * 16 + g) * 64 + dg8 * 8;
        *(float4*)&fb[base]     = make_float4(acc[ii][0].f[0], acc[ii][0].f[1],
                                              acc[ii][1].f[0], acc[ii][1].f[1]);
        *(float4*)&fb[base + 4] = make_float4(acc[ii][2].f[0], acc[ii][2].f[1],
                                              acc[ii][3].f[0], acc[ii][3].f[1]);
    }
    __syncthreads();
    if (t < 256) {
        const int rowr = t >> 4, dq = (t & 15) * 4;
        float4 sv = make_float4(0.f, 0.f, 0.f, 0.f);
#pragma unroll
        for (int gg = 0; gg < 16; gg++) {
            const float4 v = *(const float4*)&fb[(rowr * 16 + gg) * 64 + dq];
            sv.x += v.x; sv.y += v.y; sv.z += v.z; sv.w += v.w;
        }
        *(float4*)&upd[(b * Nk + i0 + rowr) * 64 + dq] = sv;
    }
}

// ---------------------------------------------------------------------------
extern "C" void kernel_launch(void* const* d_in, const int* in_sizes, int n_in,
                              void* d_out, int out_size)
{
    const float* x  = (const float*)d_in[0];
    const float* W1 = (const float*)d_in[1];
    const float* b1 = (const float*)d_in[2];
    const float* W2 = (const float*)d_in[3];

    float* upd  = (float*)d_out;                    // (B,N,H)
    float* attn = (float*)d_out + Bk * Nk * 64;     // (B,N,N)

    const int k1_smem  = 32 * 129 * 8 + 2048 * 4 + 64 * 33 * 4;  // 49664 B
    const int k2a_smem = 65536;
    const int k2b_smem = 65536 + 64;                             // reduce buf + sis
    cudaFuncSetAttribute(k1_proj,   cudaFuncAttributeMaxDynamicSharedMemorySize, k1_smem);
    cudaFuncSetAttribute(k2a_logits,cudaFuncAttributeMaxDynamicSharedMemorySize, k2a_smem);
    cudaFuncSetAttribute(k2b_av,    cudaFuncAttributeMaxDynamicSharedMemorySize, k2b_smem);

    k1_proj<<<Bk * Nk / 32, 256, k1_smem>>>(x, W1, b1);
    k2a_logits<<<Bk * 64 * 4, 256, k2a_smem>>>(W2, attn);
    k2b_av<<<Bk * 64, 512, k2b_smem>>>(x, upd, attn);
}

// round 16
// speedup vs baseline: 1.0230x; 1.0230x over previous
#include <cuda_runtime.h>
#include <math.h>

// B=4, N=1024, H=64
// out: updated (B,N,H) f32 ++ attn (B,N,N) f32
// softmax shift-invariance: b2 and max-subtraction dropped exactly.

#define Bk 4
#define Nk 1024

// scratch
__device__ float g_A[Bk * Nk * 64];      // A[b*N+i][h] = x@W1a^T + b1
__device__ float g_Ct[Bk * 64 * Nk];     // C^T plain: [b][h][j]

union F2U { float2 f2; unsigned long long u; float f[2]; };

__device__ __forceinline__ unsigned long long add2(unsigned long long a, unsigned long long b) {
    unsigned long long r;
    asm("add.rn.f32x2 %0, %1, %2;" : "=l"(r) : "l"(a), "l"(b));
    return r;
}
__device__ __forceinline__ unsigned long long fma2(unsigned long long a, unsigned long long b,
                                                   unsigned long long c) {
    unsigned long long r;
    asm("fma.rn.f32x2 %0, %1, %2, %3;" : "=l"(r) : "l"(a), "l"(b), "l"(c));
    return r;
}

// ---------------------------------------------------------------------------
// K1: projections (measured-best shape). grid = 128 blocks, 256 threads.
// ---------------------------------------------------------------------------
__global__ __launch_bounds__(256) void k1_proj(const float* __restrict__ x,
                                               const float* __restrict__ W1,
                                               const float* __restrict__ b1)
{
    extern __shared__ float sm1[];
    float2* w1p = (float2*)sm1;              // 32*129 float2: [dp][col]
    float*  xs  = sm1 + 32 * 129 * 2;        // 2048 floats
    float*  sct = xs + 2048;                 // 64*33 floats

    const int t = threadIdx.x;
    const int row0 = blockIdx.x * 32;
    const int b = row0 >> 10;
    const int j0 = row0 & 1023;
    const int tr = t >> 5;
    const int tc = t & 31;

#pragma unroll
    for (int q = 0; q < 8; q++) {
        const int idx4 = q * 256 + t;
        const int h  = idx4 >> 5;
        const int c0 = (idx4 & 31) * 4;
        const int col = (c0 < 64) ? h : h + 64;
        const int dp0 = (c0 & 63) >> 1;
        const float4 v = ((const float4*)W1)[idx4];
        w1p[(dp0 + 0) * 129 + col] = make_float2(v.x, v.y);
        w1p[(dp0 + 1) * 129 + col] = make_float2(v.z, v.w);
    }
#pragma unroll
    for (int q = 0; q < 2; q++)
        ((float4*)xs)[q * 256 + t] = ((const float4*)(x + row0 * 64))[q * 256 + t];
    __syncthreads();

    F2U acc[4][4];
#pragma unroll
    for (int r = 0; r < 4; r++)
#pragma unroll
        for (int k = 0; k < 4; k++) acc[r][k].u = 0ull;

#pragma unroll 8
    for (int dp = 0; dp < 32; dp++) {
        F2U xr[4], wc[4];
#pragma unroll
        for (int r = 0; r < 4; r++)
            xr[r].f2 = *(const float2*)&xs[(tr * 4 + r) * 64 + dp * 2];
#pragma unroll
        for (int k = 0; k < 4; k++)
            wc[k].f2 = w1p[dp * 129 + tc + k * 32];
#pragma unroll
        for (int r = 0; r < 4; r++)
#pragma unroll
            for (int k = 0; k < 4; k++)
                acc[r][k].u = fma2(xr[r].u, wc[k].u, acc[r][k].u);
    }

    const float b0  = b1[tc];
    const float b32 = b1[tc + 32];
#pragma unroll
    for (int r = 0; r < 4; r++) {
        const int jl = tr * 4 + r;
        const int row = row0 + jl;
        g_A[row * 64 + tc]      = acc[r][0].f[0] + acc[r][0].f[1] + b0;
        g_A[row * 64 + tc + 32] = acc[r][1].f[0] + acc[r][1].f[1] + b32;
        sct[tc * 33 + jl]        = acc[r][2].f[0] + acc[r][2].f[1];
        sct[(tc + 32) * 33 + jl] = acc[r][3].f[0] + acc[r][3].f[1];
    }
    __syncthreads();
#pragma unroll
    for (int q = 0; q < 8; q++) {
        const int idx = q * 256 + t;           // [h][jl], coalesced out
        const int h = idx >> 5, jl = idx & 31;
        g_Ct[b * 65536 + h * 1024 + j0 + jl] = sct[h * 33 + jl];
    }
}

// ---------------------------------------------------------------------------
// K2 fused: logits + exp (kept in smem) + block-local softmax + attn write
// (once) + updated = attn @ x.   grid = B*64 = 256 blocks, 512 threads.
//
// smem (floats): E[16*1024]=16384 ++ xs[64*68]=4352 ++ psd[16*65 f2]
//                ++ At2[64*16 f2] ++ w2d[64 f2] ++ sis[16] ++ reds[64]
// total ~98KB -> 2 blocks/SM (32 warps resident).
// ---------------------------------------------------------------------------
__global__ __launch_bounds__(512, 2) void k2_fused(const float* __restrict__ x,
                                                   const float* __restrict__ W2,
                                                   float* __restrict__ upd,
                                                   float* __restrict__ attn)
{
    extern __shared__ float sm[];
    float*  E    = sm;                                  // 16384
    float*  xs   = sm + 16384;                          // 4352
    float2* psd  = (float2*)(sm + 16384 + 4352);        // 16*65 f2
    float2* At2  = psd + 16 * 65;                       // 64*16 f2 (16B-aligned)
    float2* w2d  = At2 + 64 * 16;                       // 64 f2
    float*  sis  = (float*)(w2d + 64);                  // 16
    float*  reds = sis + 16;                            // 16*4
    float*  fb   = sm;                                  // final partials (reuses E)

    const int t = threadIdx.x;
    const int b  = blockIdx.x >> 6;
    const int i0 = (blockIdx.x & 63) * 16;

    // ---- stage A operands ----
    if (t < 64) { const float w = W2[t]; w2d[t] = make_float2(w, w); }
    if (t < 256) {
        const int il = t >> 4, h0 = (t & 15) * 4;
        float4 a4 = *(const float4*)&g_A[(b * Nk + i0 + il) * 64 + h0];
        At2[(h0 + 0) * 16 + il] = make_float2(a4.x, a4.x);
        At2[(h0 + 1) * 16 + il] = make_float2(a4.y, a4.y);
        At2[(h0 + 2) * 16 + il] = make_float2(a4.z, a4.z);
        At2[(h0 + 3) * 16 + il] = make_float2(a4.w, a4.w);
    }
    __syncthreads();

    // ---- Phase A: logits -> exp into E, accumulate row sums ----
    const int ti = t >> 7;           // 0..3 -> rows ti*4..+3
    const int tj = t & 127;          // j-quad within the 512-j pass
    const float4* __restrict__ Cb4 = (const float4*)(g_Ct + b * 65536);

    float s4[4] = {0.f, 0.f, 0.f, 0.f};

#pragma unroll
    for (int p2 = 0; p2 < 2; p2++) {
        const int j0 = p2 * 512;
        F2U accl[4], acch[4];
#pragma unroll
        for (int ii = 0; ii < 4; ii++) { accl[ii].u = 0ull; acch[ii].u = 0ull; }

#pragma unroll 8
        for (int h = 0; h < 64; h++) {
            const float4 c4 = Cb4[h * 256 + (j0 >> 2) + tj];
            F2U wv; wv.f2 = w2d[h];
            F2U cl, ch; cl.f2 = make_float2(c4.x, c4.y); ch.f2 = make_float2(c4.z, c4.w);
            const float4 a01 = *(const float4*)&At2[h * 16 + ti * 4];
            const float4 a23 = *(const float4*)&At2[h * 16 + ti * 4 + 2];
            F2U ad[4];
            ad[0].f2 = make_float2(a01.x, a01.y);
            ad[1].f2 = make_float2(a01.z, a01.w);
            ad[2].f2 = make_float2(a23.x, a23.y);
            ad[3].f2 = make_float2(a23.z, a23.w);
#pragma unroll
            for (int ii = 0; ii < 4; ii++) {
                F2U v0; v0.u = add2(ad[ii].u, cl.u);
                v0.f[0] = fmaxf(v0.f[0], 0.f); v0.f[1] = fmaxf(v0.f[1], 0.f);
                accl[ii].u = fma2(v0.u, wv.u, accl[ii].u);
                F2U v1; v1.u = add2(ad[ii].u, ch.u);
                v1.f[0] = fmaxf(v1.f[0], 0.f); v1.f[1] = fmaxf(v1.f[1], 0.f);
                acch[ii].u = fma2(v1.u, wv.u, acch[ii].u);
            }
        }
#pragma unroll
        for (int ii = 0; ii < 4; ii++) {
            float4 e;
            e.x = __expf(accl[ii].f[0]);  e.y = __expf(accl[ii].f[1]);
            e.z = __expf(acch[ii].f[0]);  e.w = __expf(acch[ii].f[1]);
            *(float4*)&E[(ti * 4 + ii) * 1024 + j0 + tj * 4] = e;
            s4[ii] += (e.x + e.y) + (e.z + e.w);
        }
    }

    // ---- block-local s reduce ----
#pragma unroll
    for (int off = 16; off > 0; off >>= 1) {
#pragma unroll
        for (int ii = 0; ii < 4; ii++)
            s4[ii] += __shfl_xor_sync(0xffffffffu, s4[ii], off);
    }
    if ((t & 31) == 0) {
        const int w = t >> 5;
#pragma unroll
        for (int ii = 0; ii < 4; ii++) reds[w * 4 + ii] = s4[ii];
    }
    __syncthreads();
    if (t < 16) {     // row r = t: warps with ti=r>>2 are w = (r>>2)*4 .. +3
        const int tig = t >> 2, ii = t & 3;
        const float ss = (reds[(tig * 4 + 0) * 4 + ii] + reds[(tig * 4 + 1) * 4 + ii])
                       + (reds[(tig * 4 + 2) * 4 + ii] + reds[(tig * 4 + 3) * 4 + ii]);
        sis[t] = 1.0f / ss;
    }
    __syncthreads();

    // ---- normalize E in-place + write final attn (once) ----
    float* __restrict__ attb = attn + (b * Nk + i0) * Nk;
    {
        const int row = t >> 5, c0 = (t & 31) * 4;
        const float si = sis[row];
        float* Er = &E[row * 1024];
        float* ar = &attb[row * Nk];
#pragma unroll
        for (int c = 0; c < 8; c++) {
            const int col = c0 + c * 128;
            float4 v = *(float4*)&Er[col];
            v.x *= si; v.y *= si; v.z *= si; v.w *= si;
            *(float4*)&Er[col] = v;
            *(float4*)&ar[col] = v;
        }
    }

    // ---- Phase B: updated = attn @ x, 16 passes of 64 j ----
    const int g   = t >> 6;           // 0..7 j-group of 8
    const int t6  = t & 63;
    const int ti2 = t6 >> 4;          // rows ti2*4..+3
    const int dg  = t6 & 15;          // d cols dg*4..+3
    const int jb  = g * 8;
    const float* __restrict__ xb = x + b * Nk * 64;

    F2U ul[4], uh[4];
#pragma unroll
    for (int ii = 0; ii < 4; ii++) { ul[ii].u = 0ull; uh[ii].u = 0ull; }

    for (int pass = 0; pass < 16; pass++) {
        const int jt = pass * 64;
        __syncthreads();
        // stage x tile [64][64] (stride 68)
#pragma unroll
        for (int q = 0; q < 2; q++) {
            const int idx4 = q * 512 + t;
            const int j = idx4 >> 4, d4 = idx4 & 15;
            *(float4*)&xs[j * 68 + d4 * 4] =
                *(const float4*)&xb[(jt + j) * 64 + d4 * 4];
        }
        // stage dup'd probabilities from E (normalized)
        {
            const int row = t >> 5, jb2 = (t & 31) * 2;
            const float2 p2v = *(const float2*)&E[row * 1024 + jt + jb2];
            psd[row * 65 + jb2]     = make_float2(p2v.x, p2v.x);
            psd[row * 65 + jb2 + 1] = make_float2(p2v.y, p2v.y);
        }
        __syncthreads();

#pragma unroll
        for (int jj = 0; jj < 8; jj++) {
            const float4 x4 = *(const float4*)&xs[(jb + jj) * 68 + dg * 4];
            F2U xl, xh; xl.f2 = make_float2(x4.x, x4.y); xh.f2 = make_float2(x4.z, x4.w);
#pragma unroll
            for (int ii = 0; ii < 4; ii++) {
                const unsigned long long p2 =
                    *(const unsigned long long*)&psd[(ti2 * 4 + ii) * 65 + jb + jj];
                ul[ii].u = fma2(p2, xl.u, ul[ii].u);
                uh[ii].u = fma2(p2, xh.u, uh[ii].u);
            }
        }
    }

    // ---- reduce 8 j-group partials (reuses E region) ----
    __syncthreads();
#pragma unroll
    for (int ii = 0; ii < 4; ii++) {
        const int row = ti2 * 4 + ii;
        float4 v = make_float4(ul[ii].f[0], ul[ii].f[1], uh[ii].f[0], uh[ii].f[1]);
        *(float4*)&fb[(row * 8 + g) * 64 + dg * 4] = v;
    }
    __syncthreads();
    if (t < 256) {
        const int rowr = t >> 4, dq = (t & 15) * 4;
        float4 sv = make_float4(0.f, 0.f, 0.f, 0.f);
#pragma unroll
        for (int gg = 0; gg < 8; gg++) {
            const float4 v = *(const float4*)&fb[(rowr * 8 + gg) * 64 + dq];
            sv.x += v.x; sv.y += v.y; sv.z += v.z; sv.w += v.w;
        }
        *(float4*)&upd[(b * Nk + i0 + rowr) * 64 + dq] = sv;
    }
}

// ---------------------------------------------------------------------------
extern "C" void kernel_launch(void* const* d_in, const int* in_sizes, int n_in,
                              void* d_out, int out_size)
{
    const float* x  = (const float*)d_in[0];
    const float* W1 = (const float*)d_in[1];
    const float* b1 = (const float*)d_in[2];
    const float* W2 = (const float*)d_in[3];

    float* upd  = (float*)d_out;                    // (B,N,H)
    float* attn = (float*)d_out + Bk * Nk * 64;     // (B,N,N)

    const int k1_smem = 32 * 129 * 8 + 2048 * 4 + 64 * 33 * 4;   // 49664 B
    const int k2_smem = (16384 + 4352) * 4 + 16 * 65 * 8 + 64 * 16 * 8 + 64 * 8 + 16 * 4 + 64 * 4;
    cudaFuncSetAttribute(k1_proj,  cudaFuncAttributeMaxDynamicSharedMemorySize, k1_smem);
    cudaFuncSetAttribute(k2_fused, cudaFuncAttributeMaxDynamicSharedMemorySize, k2_smem);

    k1_proj<<<Bk * Nk / 32, 256, k1_smem>>>(x, W1, b1);
    k2_fused<<<Bk * 64, 512, k2_smem>>>(x, W2, upd, attn);
}